// round 1
// baseline (speedup 1.0000x reference)
#include <cuda_runtime.h>
#include <math.h>

#define NN 50000
#define EE 800000
#define BB 256
#define DD 128
#define TT 8
#define KV_OFF (BB*TT*DD)

// ---------------- scratch (no allocations allowed) ----------------
__device__ float g_h[(size_t)NN*DD];        // post-attention node states
__device__ float g_KV[2*BB*TT*DD];          // Kc then Vc
__device__ float g_lip[BB*9];               // lattice inner products
__device__ float g_agg[(size_t)NN*DD];      // scatter sums
__device__ int   g_cnt[NN];                 // scatter counts

__device__ __forceinline__ float silu_f(float x) {
    return __fdividef(x, 1.f + __expf(-x));
}

// ---------------- kernel 1: K/V projection + lattice gram ----------------
__global__ void prep_kernel(const float* __restrict__ cond,
                            const float* __restrict__ wk, const float* __restrict__ bk,
                            const float* __restrict__ wv, const float* __restrict__ bv,
                            const float* __restrict__ lat)
{
    int b = blockIdx.x;
    if (b < BB*TT) {
        __shared__ float s_c[DD];
        int d = threadIdx.x;
        s_c[d] = cond[b*DD + d];
        __syncthreads();
        float ka = bk[d], va = bv[d];
        #pragma unroll 8
        for (int k = 0; k < DD; k++) {
            float c = s_c[k];
            ka = fmaf(c, wk[k*DD + d], ka);
            va = fmaf(c, wv[k*DD + d], va);
        }
        g_KV[b*DD + d] = ka;
        g_KV[KV_OFF + b*DD + d] = va;
    } else {
        int bb = b - BB*TT;
        int t = threadIdx.x;
        if (t < 9) {
            int i = t / 3, k2 = t % 3;
            const float* L = lat + bb*9;
            g_lip[bb*9 + t] = L[i*3+0]*L[k2*3+0] + L[i*3+1]*L[k2*3+1] + L[i*3+2]*L[k2*3+2];
        }
    }
}

// ---------------- kernel 2: zero scatter buffers ----------------
__global__ void zero_kernel()
{
    int idx = blockIdx.x * blockDim.x + threadIdx.x;
    if (idx < NN*DD) g_agg[idx] = 0.f;
    if (idx < NN)    g_cnt[idx] = 0;
}

// ---------------- kernel 3: cross-attention with spatial bias ----------------
// 512 threads = 4 nodes x 128 lanes, persistent blocks, weights in smem.
__global__ __launch_bounds__(512, 1)
void attn_kernel(const float* __restrict__ nfeat, const float* __restrict__ frac,
                 const int* __restrict__ n2g,
                 const float* __restrict__ wq, const float* __restrict__ bq,
                 const float* __restrict__ wo, const float* __restrict__ bo,
                 const float* __restrict__ sw1, const float* __restrict__ sb1,
                 const float* __restrict__ sw2, const float* __restrict__ sb2)
{
    extern __shared__ float sm[];
    float* s_wq  = sm;                 // 16384
    float* s_wo  = s_wq + 16384;       // 16384
    float* s_sw1 = s_wo + 16384;       // 3072
    float* s_sw2 = s_sw1 + 3072;       // 1024
    float* s_bq  = s_sw2 + 1024;       // 128
    float* s_bo  = s_bq + 128;         // 128
    float* s_sb1 = s_bo + 128;         // 128
    float* s_sb2 = s_sb1 + 128;        // 8
    float* s_h   = s_sb2 + 8;          // 512
    float* s_q   = s_h + 512;          // 512
    float* s_hid = s_q + 512;          // 512
    float* s_ca  = s_hid + 512;        // 512
    float* s_enc = s_ca + 512;         // 96
    float* s_att = s_enc + 96;         // 32

    int tid = threadIdx.x;
    for (int i = tid; i < 16384; i += 512) { s_wq[i] = wq[i]; s_wo[i] = wo[i]; }
    for (int i = tid; i < 3072; i += 512) s_sw1[i] = sw1[i];
    for (int i = tid; i < 1024; i += 512) s_sw2[i] = sw2[i];
    if (tid < 128) { s_bq[tid] = bq[tid]; s_bo[tid] = bo[tid]; s_sb1[tid] = sb1[tid]; }
    if (tid < 8) s_sb2[tid] = sb2[tid];
    __syncthreads();

    int sub = tid >> 7, d = tid & 127;
    int ngroups = (NN + 3) >> 2;
    for (int grp = blockIdx.x; grp < ngroups; grp += gridDim.x) {
        int n = grp*4 + sub;
        bool act = n < NN;
        int g = act ? n2g[n] : 0;
        float hv = act ? nfeat[(size_t)n*DD + d] : 0.f;
        s_h[sub*DD + d] = hv;
        if (d < 24 && act) {
            int ii = d % 12, c = ii >> 2, j = ii & 3;
            float ph = frac[n*3 + c] * ((float)(1 << j) * 3.14159265358979323846f);
            s_enc[sub*24 + d] = (d < 12) ? sinf(ph) : cosf(ph);
        }
        __syncthreads();

        // Q = h @ wq + bq ; hidden = silu(enc @ sw1 + sb1)
        {
            float acc = s_bq[d];
            const float* hh = s_h + sub*DD;
            #pragma unroll 8
            for (int k = 0; k < DD; k++) acc = fmaf(hh[k], s_wq[k*DD + d], acc);
            s_q[sub*DD + d] = acc;
            float ha = s_sb1[d];
            const float* ee = s_enc + sub*24;
            #pragma unroll
            for (int k = 0; k < 24; k++) ha = fmaf(ee[k], s_sw1[k*DD + d], ha);
            s_hid[sub*DD + d] = silu_f(ha);
        }
        __syncthreads();

        // scores + bias (16 lanes per t), shuffle reduce
        {
            int t = d >> 4, lane = d & 15;
            float sc = 0.f, bi = 0.f;
            const float* Kr = g_KV + ((size_t)(g*TT + t))*DD;
            const float* qq = s_q + sub*DD;
            const float* hh2 = s_hid + sub*DD;
            #pragma unroll
            for (int k = lane; k < DD; k += 16) {
                sc = fmaf(qq[k], Kr[k], sc);
                bi = fmaf(hh2[k], s_sw2[k*8 + t], bi);
            }
            #pragma unroll
            for (int o = 8; o > 0; o >>= 1) {
                sc += __shfl_down_sync(0xffffffffu, sc, o, 16);
                bi += __shfl_down_sync(0xffffffffu, bi, o, 16);
            }
            if (lane == 0)
                s_att[sub*8 + t] = sc * 0.08838834764831845f + bi + s_sb2[t];
        }
        __syncthreads();
        if (d == 0) {  // softmax over 8 (single thread per node)
            float* a = s_att + sub*8;
            float m = a[0];
            #pragma unroll
            for (int u = 1; u < 8; u++) m = fmaxf(m, a[u]);
            float s = 0.f, ex[8];
            #pragma unroll
            for (int u = 0; u < 8; u++) { ex[u] = __expf(a[u] - m); s += ex[u]; }
            float inv = __fdividef(1.f, s);
            #pragma unroll
            for (int u = 0; u < 8; u++) a[u] = ex[u] * inv;
        }
        __syncthreads();
        // ca = attn @ V
        {
            const float* Vr = g_KV + KV_OFF + ((size_t)(g*TT))*DD;
            float ca = 0.f;
            #pragma unroll
            for (int u = 0; u < 8; u++) ca = fmaf(s_att[sub*8 + u], Vr[u*DD + d], ca);
            s_ca[sub*DD + d] = ca;
        }
        __syncthreads();
        // h = h + ca @ wo + bo
        {
            float out = hv + s_bo[d];
            const float* cc = s_ca + sub*DD;
            #pragma unroll 8
            for (int k = 0; k < DD; k++) out = fmaf(cc[k], s_wo[k*DD + d], out);
            if (act) g_h[(size_t)n*DD + d] = out;
        }
        __syncthreads();
    }
}

// ---------------- kernel 4: edge MLP + atomic scatter ----------------
#define TILE_E 64
#define P1 273   // gather tile pitch (odd -> low bank conflict)
#define P2 133   // hidden tile pitch

__global__ __launch_bounds__(256)
void edge_kernel(const float* __restrict__ frac,
                 const int* __restrict__ edges, const int* __restrict__ e2g,
                 const float* __restrict__ ew1, const float* __restrict__ eb1,
                 const float* __restrict__ ew2, const float* __restrict__ eb2)
{
    extern __shared__ float sm[];
    float* s_a = sm;                    // TILE_E*P1 floats; reused pitch P2 for hidden
    float* s_b = sm + TILE_E*P1;        // 8*128
    __shared__ int s_i[TILE_E], s_j[TILE_E], s_g[TILE_E];

    int tid = threadIdx.x;
    int e0 = blockIdx.x * TILE_E;
    if (tid < TILE_E) {
        s_i[tid] = edges[e0 + tid];
        s_j[tid] = edges[EE + e0 + tid];
        s_g[tid] = e2g[e0 + tid];
    }
    __syncthreads();

    // gather h_i / h_j rows (coalesced, L2-resident)
    {
        int subr = tid >> 7, lane = tid & 127;
        for (int ee = subr; ee < TILE_E; ee += 2) {
            s_a[ee*P1 + lane]      = g_h[(size_t)s_i[ee]*DD + lane];
            s_a[ee*P1 + DD + lane] = g_h[(size_t)s_j[ee]*DD + lane];
        }
    }
    if (tid < TILE_E) {
        int e = tid;
        const float* lp = g_lip + s_g[e]*9;
        #pragma unroll
        for (int u = 0; u < 9; u++) s_a[e*P1 + 256 + u] = lp[u];
        int ii = s_i[e], jj = s_j[e];
        #pragma unroll
        for (int c = 0; c < 3; c++) {
            float dd = frac[jj*3 + c] - frac[ii*3 + c];
            dd -= floorf(dd);
            s_a[e*P1 + 265 + c] = dd;
        }
        #pragma unroll
        for (int u = 268; u < 272; u++) s_a[e*P1 + u] = 0.f;
        atomicAdd(&g_cnt[ii], 1);
    }

    int tx = tid & 15, ty = tid >> 4;
    int col0 = tx * 8;
    int lrow = tid >> 5;           // b-tile coop-load row 0..7
    int lcol = (tid & 31) * 4;     // b-tile coop-load col (float4)

    float acc[4][8];
    #pragma unroll
    for (int i = 0; i < 4; i++)
        #pragma unroll
        for (int u = 0; u < 8; u++) acc[i][u] = 0.f;

    // GEMM1: [64,272] x [272,128]  (rows >= 268 are zero-padded)
    for (int kt = 0; kt < 272; kt += 8) {
        __syncthreads();
        int kr = kt + lrow;
        float4 v = (kr < 268) ? *(const float4*)(ew1 + kr*DD + lcol)
                              : make_float4(0.f, 0.f, 0.f, 0.f);
        *(float4*)(s_b + lrow*DD + lcol) = v;
        __syncthreads();
        #pragma unroll
        for (int k = 0; k < 8; k++) {
            float a0 = s_a[(ty*4+0)*P1 + kt + k];
            float a1 = s_a[(ty*4+1)*P1 + kt + k];
            float a2 = s_a[(ty*4+2)*P1 + kt + k];
            float a3 = s_a[(ty*4+3)*P1 + kt + k];
            float4 b0 = *(const float4*)(s_b + k*DD + col0);
            float4 b1 = *(const float4*)(s_b + k*DD + col0 + 4);
            float bb[8] = {b0.x, b0.y, b0.z, b0.w, b1.x, b1.y, b1.z, b1.w};
            #pragma unroll
            for (int u = 0; u < 8; u++) {
                acc[0][u] = fmaf(a0, bb[u], acc[0][u]);
                acc[1][u] = fmaf(a1, bb[u], acc[1][u]);
                acc[2][u] = fmaf(a2, bb[u], acc[2][u]);
                acc[3][u] = fmaf(a3, bb[u], acc[3][u]);
            }
        }
    }

    // silu + bias -> hidden tile (reuse s_a with pitch P2)
    {
        float eb[8];
        #pragma unroll
        for (int u = 0; u < 8; u++) eb[u] = eb1[col0 + u];
        __syncthreads();
        #pragma unroll
        for (int i = 0; i < 4; i++)
            #pragma unroll
            for (int u = 0; u < 8; u++) {
                s_a[(ty*4+i)*P2 + col0 + u] = silu_f(acc[i][u] + eb[u]);
                acc[i][u] = 0.f;
            }
    }

    // GEMM2: [64,128] x [128,128]
    for (int kt = 0; kt < 128; kt += 8) {
        __syncthreads();
        *(float4*)(s_b + lrow*DD + lcol) = *(const float4*)(ew2 + (kt+lrow)*DD + lcol);
        __syncthreads();
        #pragma unroll
        for (int k = 0; k < 8; k++) {
            float a0 = s_a[(ty*4+0)*P2 + kt + k];
            float a1 = s_a[(ty*4+1)*P2 + kt + k];
            float a2 = s_a[(ty*4+2)*P2 + kt + k];
            float a3 = s_a[(ty*4+3)*P2 + kt + k];
            float4 b0 = *(const float4*)(s_b + k*DD + col0);
            float4 b1 = *(const float4*)(s_b + k*DD + col0 + 4);
            float bb[8] = {b0.x, b0.y, b0.z, b0.w, b1.x, b1.y, b1.z, b1.w};
            #pragma unroll
            for (int u = 0; u < 8; u++) {
                acc[0][u] = fmaf(a0, bb[u], acc[0][u]);
                acc[1][u] = fmaf(a1, bb[u], acc[1][u]);
                acc[2][u] = fmaf(a2, bb[u], acc[2][u]);
                acc[3][u] = fmaf(a3, bb[u], acc[3][u]);
            }
        }
    }

    // silu + bias, atomic scatter-add into agg
    {
        float eb[8];
        #pragma unroll
        for (int u = 0; u < 8; u++) eb[u] = eb2[col0 + u];
        #pragma unroll
        for (int i = 0; i < 4; i++) {
            int dst = s_i[ty*4 + i];
            float* ap = g_agg + (size_t)dst*DD + col0;
            #pragma unroll
            for (int u = 0; u < 8; u++)
                atomicAdd(ap + u, silu_f(acc[i][u] + eb[u]));
        }
    }
}

// ---------------- kernel 5: node MLP + residual ----------------
__global__ __launch_bounds__(512, 1)
void node_kernel(const float* __restrict__ nfeat,
                 const float* __restrict__ nw1, const float* __restrict__ nb1,
                 const float* __restrict__ nw2, const float* __restrict__ nb2,
                 float* __restrict__ out)
{
    extern __shared__ float sm[];
    float* s_w1 = sm;              // 32768
    float* s_w2 = s_w1 + 32768;    // 16384
    float* s_b1 = s_w2 + 16384;    // 128
    float* s_b2 = s_b1 + 128;      // 128
    float* s_in = s_b2 + 128;      // 4*256
    float* s_hd = s_in + 1024;     // 4*128

    int tid = threadIdx.x;
    for (int i = tid; i < 32768; i += 512) s_w1[i] = nw1[i];
    for (int i = tid; i < 16384; i += 512) s_w2[i] = nw2[i];
    if (tid < 128) { s_b1[tid] = nb1[tid]; s_b2[tid] = nb2[tid]; }
    __syncthreads();

    int sub = tid >> 7, d = tid & 127;
    int ng = (NN + 3) >> 2;
    for (int grp = blockIdx.x; grp < ng; grp += gridDim.x) {
        int n = grp*4 + sub;
        bool act = n < NN;
        if (act) {
            float cnt = fmaxf((float)g_cnt[n], 1.f);
            s_in[sub*256 + d]       = g_h[(size_t)n*DD + d];
            s_in[sub*256 + 128 + d] = __fdividef(g_agg[(size_t)n*DD + d], cnt);
        }
        __syncthreads();
        float a = s_b1[d];
        const float* xin = s_in + sub*256;
        #pragma unroll 8
        for (int k = 0; k < 256; k++) a = fmaf(xin[k], s_w1[k*DD + d], a);
        s_hd[sub*DD + d] = silu_f(a);
        __syncthreads();
        float a2 = s_b2[d];
        const float* xh = s_hd + sub*DD;
        #pragma unroll 8
        for (int k = 0; k < DD; k++) a2 = fmaf(xh[k], s_w2[k*DD + d], a2);
        if (act) out[(size_t)n*DD + d] = nfeat[(size_t)n*DD + d] + silu_f(a2);
        __syncthreads();
    }
}

// ---------------- launch ----------------
extern "C" void kernel_launch(void* const* d_in, const int* in_sizes, int n_in,
                              void* d_out, int out_size)
{
    const float* node_features = (const float*)d_in[0];
    const float* cond = (const float*)d_in[1];
    const int*   n2g  = (const int*)d_in[2];
    const float* frac = (const float*)d_in[3];
    const float* lat  = (const float*)d_in[4];
    const int*   edges= (const int*)d_in[5];
    const int*   e2g  = (const int*)d_in[6];
    const float* wq = (const float*)d_in[7];
    const float* bq = (const float*)d_in[8];
    const float* wk = (const float*)d_in[9];
    const float* bk = (const float*)d_in[10];
    const float* wv = (const float*)d_in[11];
    const float* bv = (const float*)d_in[12];
    const float* wo = (const float*)d_in[13];
    const float* bo = (const float*)d_in[14];
    const float* sw1= (const float*)d_in[15];
    const float* sb1= (const float*)d_in[16];
    const float* sw2= (const float*)d_in[17];
    const float* sb2= (const float*)d_in[18];
    const float* ew1= (const float*)d_in[19];
    const float* eb1= (const float*)d_in[20];
    const float* ew2= (const float*)d_in[21];
    const float* eb2= (const float*)d_in[22];
    const float* nw1= (const float*)d_in[23];
    const float* nb1= (const float*)d_in[24];
    const float* nw2= (const float*)d_in[25];
    const float* nb2= (const float*)d_in[26];
    float* out = (float*)d_out;

    const int attn_smem = 39432 * 4;
    const int edge_smem = (TILE_E*P1 + 8*DD) * 4;
    const int node_smem = 50944 * 4;
    cudaFuncSetAttribute(attn_kernel, cudaFuncAttributeMaxDynamicSharedMemorySize, attn_smem);
    cudaFuncSetAttribute(edge_kernel, cudaFuncAttributeMaxDynamicSharedMemorySize, edge_smem);
    cudaFuncSetAttribute(node_kernel, cudaFuncAttributeMaxDynamicSharedMemorySize, node_smem);

    prep_kernel<<<BB*TT + BB, 128>>>(cond, wk, bk, wv, bv, lat);
    zero_kernel<<<(NN*DD + 255) / 256, 256>>>();
    attn_kernel<<<152, 512, attn_smem>>>(node_features, frac, n2g,
                                         wq, bq, wo, bo, sw1, sb1, sw2, sb2);
    edge_kernel<<<EE / TILE_E, 256, edge_smem>>>(frac, edges, e2g, ew1, eb1, ew2, eb2);
    node_kernel<<<152, 512, node_smem>>>(node_features, nw1, nb1, nw2, nb2, out);
}

// round 2
// speedup vs baseline: 1.4351x; 1.4351x over previous
#include <cuda_runtime.h>
#include <math.h>
#include <stdint.h>

#define NN 50000
#define EE 800000
#define BB 256
#define DD 128
#define TT 8
#define KV_OFF (BB*TT*DD)

// ---------------- scratch (no allocations allowed) ----------------
__device__ float g_h[(size_t)NN*DD];        // post-attention node states
__device__ float g_KV[2*BB*TT*DD];          // Kc then Vc
__device__ float g_lip[BB*9];               // lattice inner products
__device__ float g_agg[(size_t)NN*DD];      // scatter sums
__device__ int   g_cnt[NN];                 // scatter counts

__device__ __forceinline__ float silu_f(float x) {
    return __fdividef(x, 1.f + __expf(-x));
}

__device__ __forceinline__ float to_tf32(float x) {
    uint32_t t;
    asm("cvt.rna.tf32.f32 %0, %1;" : "=r"(t) : "f"(x));
    return __uint_as_float(t);
}

__device__ __forceinline__ void mma_tf32(float* c, const uint32_t* a, const uint32_t* b) {
    asm volatile(
        "mma.sync.aligned.m16n8k8.row.col.f32.tf32.tf32.f32 "
        "{%0,%1,%2,%3}, {%4,%5,%6,%7}, {%8,%9}, {%0,%1,%2,%3};\n"
        : "+f"(c[0]), "+f"(c[1]), "+f"(c[2]), "+f"(c[3])
        : "r"(a[0]), "r"(a[1]), "r"(a[2]), "r"(a[3]), "r"(b[0]), "r"(b[1]));
}

// ---------------- kernel 1: K/V projection + lattice gram ----------------
__global__ void prep_kernel(const float* __restrict__ cond,
                            const float* __restrict__ wk, const float* __restrict__ bk,
                            const float* __restrict__ wv, const float* __restrict__ bv,
                            const float* __restrict__ lat)
{
    int b = blockIdx.x;
    if (b < BB*TT) {
        __shared__ float s_c[DD];
        int d = threadIdx.x;
        s_c[d] = cond[b*DD + d];
        __syncthreads();
        float ka = bk[d], va = bv[d];
        #pragma unroll 8
        for (int k = 0; k < DD; k++) {
            float c = s_c[k];
            ka = fmaf(c, wk[k*DD + d], ka);
            va = fmaf(c, wv[k*DD + d], va);
        }
        g_KV[b*DD + d] = ka;
        g_KV[KV_OFF + b*DD + d] = va;
    } else {
        int bb = b - BB*TT;
        int t = threadIdx.x;
        if (t < 9) {
            int i = t / 3, k2 = t % 3;
            const float* L = lat + bb*9;
            g_lip[bb*9 + t] = L[i*3+0]*L[k2*3+0] + L[i*3+1]*L[k2*3+1] + L[i*3+2]*L[k2*3+2];
        }
    }
}

// ---------------- kernel 2: zero scatter buffers ----------------
__global__ void zero_kernel()
{
    int idx = blockIdx.x * blockDim.x + threadIdx.x;
    if (idx < NN*DD) g_agg[idx] = 0.f;
    if (idx < NN)    g_cnt[idx] = 0;
}

// ---------------- kernel 3: cross-attention with spatial bias ----------------
__global__ __launch_bounds__(512, 1)
void attn_kernel(const float* __restrict__ nfeat, const float* __restrict__ frac,
                 const int* __restrict__ n2g,
                 const float* __restrict__ wq, const float* __restrict__ bq,
                 const float* __restrict__ wo, const float* __restrict__ bo,
                 const float* __restrict__ sw1, const float* __restrict__ sb1,
                 const float* __restrict__ sw2, const float* __restrict__ sb2)
{
    extern __shared__ float sm[];
    float* s_wq  = sm;                 // 16384
    float* s_wo  = s_wq + 16384;       // 16384
    float* s_sw1 = s_wo + 16384;       // 3072
    float* s_sw2 = s_sw1 + 3072;       // 1024
    float* s_bq  = s_sw2 + 1024;       // 128
    float* s_bo  = s_bq + 128;         // 128
    float* s_sb1 = s_bo + 128;         // 128
    float* s_sb2 = s_sb1 + 128;        // 8
    float* s_h   = s_sb2 + 8;          // 512
    float* s_q   = s_h + 512;          // 512
    float* s_hid = s_q + 512;          // 512
    float* s_ca  = s_hid + 512;        // 512
    float* s_enc = s_ca + 512;         // 96
    float* s_att = s_enc + 96;         // 32

    int tid = threadIdx.x;
    for (int i = tid; i < 16384; i += 512) { s_wq[i] = wq[i]; s_wo[i] = wo[i]; }
    for (int i = tid; i < 3072; i += 512) s_sw1[i] = sw1[i];
    for (int i = tid; i < 1024; i += 512) s_sw2[i] = sw2[i];
    if (tid < 128) { s_bq[tid] = bq[tid]; s_bo[tid] = bo[tid]; s_sb1[tid] = sb1[tid]; }
    if (tid < 8) s_sb2[tid] = sb2[tid];
    __syncthreads();

    int sub = tid >> 7, d = tid & 127;
    int ngroups = (NN + 3) >> 2;
    for (int grp = blockIdx.x; grp < ngroups; grp += gridDim.x) {
        int n = grp*4 + sub;
        bool act = n < NN;
        int g = act ? n2g[n] : 0;
        float hv = act ? nfeat[(size_t)n*DD + d] : 0.f;
        s_h[sub*DD + d] = hv;
        if (d < 24 && act) {
            int ii = d % 12, c = ii >> 2, j = ii & 3;
            float ph = frac[n*3 + c] * ((float)(1 << j) * 3.14159265358979323846f);
            s_enc[sub*24 + d] = (d < 12) ? sinf(ph) : cosf(ph);
        }
        __syncthreads();

        {
            float acc = s_bq[d];
            const float* hh = s_h + sub*DD;
            #pragma unroll 8
            for (int k = 0; k < DD; k++) acc = fmaf(hh[k], s_wq[k*DD + d], acc);
            s_q[sub*DD + d] = acc;
            float ha = s_sb1[d];
            const float* ee = s_enc + sub*24;
            #pragma unroll
            for (int k = 0; k < 24; k++) ha = fmaf(ee[k], s_sw1[k*DD + d], ha);
            s_hid[sub*DD + d] = silu_f(ha);
        }
        __syncthreads();

        {
            int t = d >> 4, lane = d & 15;
            float sc = 0.f, bi = 0.f;
            const float* Kr = g_KV + ((size_t)(g*TT + t))*DD;
            const float* qq = s_q + sub*DD;
            const float* hh2 = s_hid + sub*DD;
            #pragma unroll
            for (int k = lane; k < DD; k += 16) {
                sc = fmaf(qq[k], Kr[k], sc);
                bi = fmaf(hh2[k], s_sw2[k*8 + t], bi);
            }
            #pragma unroll
            for (int o = 8; o > 0; o >>= 1) {
                sc += __shfl_down_sync(0xffffffffu, sc, o, 16);
                bi += __shfl_down_sync(0xffffffffu, bi, o, 16);
            }
            if (lane == 0)
                s_att[sub*8 + t] = sc * 0.08838834764831845f + bi + s_sb2[t];
        }
        __syncthreads();
        if (d == 0) {
            float* a = s_att + sub*8;
            float m = a[0];
            #pragma unroll
            for (int u = 1; u < 8; u++) m = fmaxf(m, a[u]);
            float s = 0.f, ex[8];
            #pragma unroll
            for (int u = 0; u < 8; u++) { ex[u] = __expf(a[u] - m); s += ex[u]; }
            float inv = __fdividef(1.f, s);
            #pragma unroll
            for (int u = 0; u < 8; u++) a[u] = ex[u] * inv;
        }
        __syncthreads();
        {
            const float* Vr = g_KV + KV_OFF + ((size_t)(g*TT))*DD;
            float ca = 0.f;
            #pragma unroll
            for (int u = 0; u < 8; u++) ca = fmaf(s_att[sub*8 + u], Vr[u*DD + d], ca);
            s_ca[sub*DD + d] = ca;
        }
        __syncthreads();
        {
            float out = hv + s_bo[d];
            const float* cc = s_ca + sub*DD;
            #pragma unroll 8
            for (int k = 0; k < DD; k++) out = fmaf(cc[k], s_wo[k*DD + d], out);
            if (act) g_h[(size_t)n*DD + d] = out;
        }
        __syncthreads();
    }
}

// ---------------- kernel 4: edge MLP via tf32 mma.sync + atomic scatter ----------------
// Tile: 128 edges x 128 outs. 8 warps (2x4). Warp tile 64x32 = 4 mfrag x 4 nfrag of m16n8k8.
#define TM 128
#define SA 276     // A smem row stride (floats); 276%32=20 -> conflict-free frag loads
#define SB 136     // B smem row stride (floats); 136%32=8  -> conflict-free frag loads

__global__ __launch_bounds__(256, 1)
void edge_kernel(const float* __restrict__ frac,
                 const int* __restrict__ edges, const int* __restrict__ e2g,
                 const float* __restrict__ ew1, const float* __restrict__ eb1,
                 const float* __restrict__ ew2, const float* __restrict__ eb2)
{
    extern __shared__ float sm[];
    float* s_a = sm;             // TM * SA   (141,312 B)
    float* s_b = sm + TM*SA;     // 128 * SB  ( 69,632 B)
    __shared__ int s_i[TM], s_j[TM];

    int tid  = threadIdx.x;
    int lane = tid & 31;
    int wid  = tid >> 5;
    int wm = wid >> 2;           // 0..1
    int wn = wid & 3;            // 0..3
    int e0 = blockIdx.x * TM;

    if (tid < TM) {
        s_i[tid] = edges[e0 + tid];
        s_j[tid] = edges[EE + e0 + tid];
    }
    __syncthreads();

    // ---- gather A = [h_i | h_j | lip | fd | 0pad], tf32-converted ----
    for (int idx = tid; idx < TM*DD; idx += 256) {
        int e = idx >> 7, c = idx & 127;
        s_a[e*SA + c]      = to_tf32(g_h[(size_t)s_i[e]*DD + c]);
        s_a[e*SA + DD + c] = to_tf32(g_h[(size_t)s_j[e]*DD + c]);
    }
    if (tid < TM) {
        int e = tid;
        const float* lp = g_lip + e2g[e0 + e]*9;
        #pragma unroll
        for (int u = 0; u < 9; u++) s_a[e*SA + 256 + u] = to_tf32(lp[u]);
        int ii = s_i[e], jj = s_j[e];
        #pragma unroll
        for (int c = 0; c < 3; c++) {
            float dd = frac[jj*3 + c] - frac[ii*3 + c];
            dd -= floorf(dd);
            s_a[e*SA + 265 + c] = to_tf32(dd);
        }
        #pragma unroll
        for (int u = 268; u < 276; u++) s_a[e*SA + u] = 0.f;
        atomicAdd(&g_cnt[ii], 1);
    }

    float acc[4][4][4];
    #pragma unroll
    for (int mf = 0; mf < 4; mf++)
        #pragma unroll
        for (int nf = 0; nf < 4; nf++)
            #pragma unroll
            for (int u = 0; u < 4; u++) acc[mf][nf][u] = 0.f;

    // ---- GEMM1: [128,272] x [272,128], K chunks of 16 ----
    for (int kt = 0; kt < 272; kt += 16) {
        __syncthreads();
        #pragma unroll
        for (int r = 0; r < 2; r++) {
            int v = tid + r*256;                 // float4 index, 512 total
            int row = v >> 5, col = (v & 31) << 2;
            int kr = kt + row;
            float4 w = (kr < 268) ? *(const float4*)(ew1 + (size_t)kr*DD + col)
                                  : make_float4(0.f, 0.f, 0.f, 0.f);
            float* dst = s_b + row*SB + col;
            dst[0] = to_tf32(w.x); dst[1] = to_tf32(w.y);
            dst[2] = to_tf32(w.z); dst[3] = to_tf32(w.w);
        }
        __syncthreads();
        #pragma unroll
        for (int kk = 0; kk < 16; kk += 8) {
            int ktg = kt + kk;
            uint32_t afr[4][4];
            #pragma unroll
            for (int mf = 0; mf < 4; mf++) {
                const float* ap = s_a + (wm*64 + mf*16 + (lane >> 2))*SA + ktg + (lane & 3);
                afr[mf][0] = __float_as_uint(ap[0]);
                afr[mf][1] = __float_as_uint(ap[8*SA]);
                afr[mf][2] = __float_as_uint(ap[4]);
                afr[mf][3] = __float_as_uint(ap[8*SA + 4]);
            }
            uint32_t bfr[4][2];
            #pragma unroll
            for (int nf = 0; nf < 4; nf++) {
                const float* bp = s_b + (kk + (lane & 3))*SB + wn*32 + nf*8 + (lane >> 2);
                bfr[nf][0] = __float_as_uint(bp[0]);
                bfr[nf][1] = __float_as_uint(bp[4*SB]);
            }
            #pragma unroll
            for (int mf = 0; mf < 4; mf++)
                #pragma unroll
                for (int nf = 0; nf < 4; nf++)
                    mma_tf32(acc[mf][nf], afr[mf], bfr[nf]);
        }
    }

    __syncthreads();

    // ---- load full ew2 [128,128] into s_b; write hidden into s_a cols 0..127 ----
    #pragma unroll
    for (int r = 0; r < 16; r++) {
        int v = tid + r*256;                     // 4096 float4 total
        int row = v >> 5, col = (v & 31) << 2;
        float4 w = *(const float4*)(ew2 + (size_t)row*DD + col);
        float* dst = s_b + row*SB + col;
        dst[0] = to_tf32(w.x); dst[1] = to_tf32(w.y);
        dst[2] = to_tf32(w.z); dst[3] = to_tf32(w.w);
    }
    #pragma unroll
    for (int mf = 0; mf < 4; mf++) {
        int rbase = wm*64 + mf*16 + (lane >> 2);
        #pragma unroll
        for (int nf = 0; nf < 4; nf++) {
            int n = wn*32 + nf*8 + (lane & 3)*2;
            float b0 = eb1[n], b1 = eb1[n + 1];
            s_a[rbase*SA + n]           = to_tf32(silu_f(acc[mf][nf][0] + b0));
            s_a[rbase*SA + n + 1]       = to_tf32(silu_f(acc[mf][nf][1] + b1));
            s_a[(rbase + 8)*SA + n]     = to_tf32(silu_f(acc[mf][nf][2] + b0));
            s_a[(rbase + 8)*SA + n + 1] = to_tf32(silu_f(acc[mf][nf][3] + b1));
            #pragma unroll
            for (int u = 0; u < 4; u++) acc[mf][nf][u] = 0.f;
        }
    }
    __syncthreads();

    // ---- GEMM2: [128,128] x [128,128], ew2 fully resident ----
    #pragma unroll 2
    for (int kk = 0; kk < 128; kk += 8) {
        uint32_t afr[4][4];
        #pragma unroll
        for (int mf = 0; mf < 4; mf++) {
            const float* ap = s_a + (wm*64 + mf*16 + (lane >> 2))*SA + kk + (lane & 3);
            afr[mf][0] = __float_as_uint(ap[0]);
            afr[mf][1] = __float_as_uint(ap[8*SA]);
            afr[mf][2] = __float_as_uint(ap[4]);
            afr[mf][3] = __float_as_uint(ap[8*SA + 4]);
        }
        uint32_t bfr[4][2];
        #pragma unroll
        for (int nf = 0; nf < 4; nf++) {
            const float* bp = s_b + (kk + (lane & 3))*SB + wn*32 + nf*8 + (lane >> 2);
            bfr[nf][0] = __float_as_uint(bp[0]);
            bfr[nf][1] = __float_as_uint(bp[4*SB]);
        }
        #pragma unroll
        for (int mf = 0; mf < 4; mf++)
            #pragma unroll
            for (int nf = 0; nf < 4; nf++)
                mma_tf32(acc[mf][nf], afr[mf], bfr[nf]);
    }

    // ---- epilogue: silu + bias, vector red scatter into g_agg ----
    #pragma unroll
    for (int mf = 0; mf < 4; mf++) {
        #pragma unroll
        for (int rr = 0; rr < 2; rr++) {
            int m = wm*64 + mf*16 + (lane >> 2) + rr*8;
            float* ap = g_agg + (size_t)s_i[m]*DD;
            #pragma unroll
            for (int nf = 0; nf < 4; nf++) {
                int n = wn*32 + nf*8 + (lane & 3)*2;
                float v0 = silu_f(acc[mf][nf][rr*2 + 0] + eb2[n]);
                float v1 = silu_f(acc[mf][nf][rr*2 + 1] + eb2[n + 1]);
                asm volatile("red.global.add.v2.f32 [%0], {%1, %2};"
                             :: "l"(ap + n), "f"(v0), "f"(v1) : "memory");
            }
        }
    }
}

// ---------------- kernel 5: node MLP + residual ----------------
__global__ __launch_bounds__(512, 1)
void node_kernel(const float* __restrict__ nfeat,
                 const float* __restrict__ nw1, const float* __restrict__ nb1,
                 const float* __restrict__ nw2, const float* __restrict__ nb2,
                 float* __restrict__ out)
{
    extern __shared__ float sm[];
    float* s_w1 = sm;              // 32768
    float* s_w2 = s_w1 + 32768;    // 16384
    float* s_b1 = s_w2 + 16384;    // 128
    float* s_b2 = s_b1 + 128;      // 128
    float* s_in = s_b2 + 128;      // 4*256
    float* s_hd = s_in + 1024;     // 4*128

    int tid = threadIdx.x;
    for (int i = tid; i < 32768; i += 512) s_w1[i] = nw1[i];
    for (int i = tid; i < 16384; i += 512) s_w2[i] = nw2[i];
    if (tid < 128) { s_b1[tid] = nb1[tid]; s_b2[tid] = nb2[tid]; }
    __syncthreads();

    int sub = tid >> 7, d = tid & 127;
    int ng = (NN + 3) >> 2;
    for (int grp = blockIdx.x; grp < ng; grp += gridDim.x) {
        int n = grp*4 + sub;
        bool act = n < NN;
        if (act) {
            float cnt = fmaxf((float)g_cnt[n], 1.f);
            s_in[sub*256 + d]       = g_h[(size_t)n*DD + d];
            s_in[sub*256 + 128 + d] = __fdividef(g_agg[(size_t)n*DD + d], cnt);
        }
        __syncthreads();
        float a = s_b1[d];
        const float* xin = s_in + sub*256;
        #pragma unroll 8
        for (int k = 0; k < 256; k++) a = fmaf(xin[k], s_w1[k*DD + d], a);
        s_hd[sub*DD + d] = silu_f(a);
        __syncthreads();
        float a2 = s_b2[d];
        const float* xh = s_hd + sub*DD;
        #pragma unroll 8
        for (int k = 0; k < DD; k++) a2 = fmaf(xh[k], s_w2[k*DD + d], a2);
        if (act) out[(size_t)n*DD + d] = nfeat[(size_t)n*DD + d] + silu_f(a2);
        __syncthreads();
    }
}

// ---------------- launch ----------------
extern "C" void kernel_launch(void* const* d_in, const int* in_sizes, int n_in,
                              void* d_out, int out_size)
{
    const float* node_features = (const float*)d_in[0];
    const float* cond = (const float*)d_in[1];
    const int*   n2g  = (const int*)d_in[2];
    const float* frac = (const float*)d_in[3];
    const float* lat  = (const float*)d_in[4];
    const int*   edges= (const int*)d_in[5];
    const int*   e2g  = (const int*)d_in[6];
    const float* wq = (const float*)d_in[7];
    const float* bq = (const float*)d_in[8];
    const float* wk = (const float*)d_in[9];
    const float* bk = (const float*)d_in[10];
    const float* wv = (const float*)d_in[11];
    const float* bv = (const float*)d_in[12];
    const float* wo = (const float*)d_in[13];
    const float* bo = (const float*)d_in[14];
    const float* sw1= (const float*)d_in[15];
    const float* sb1= (const float*)d_in[16];
    const float* sw2= (const float*)d_in[17];
    const float* sb2= (const float*)d_in[18];
    const float* ew1= (const float*)d_in[19];
    const float* eb1= (const float*)d_in[20];
    const float* ew2= (const float*)d_in[21];
    const float* eb2= (const float*)d_in[22];
    const float* nw1= (const float*)d_in[23];
    const float* nb1= (const float*)d_in[24];
    const float* nw2= (const float*)d_in[25];
    const float* nb2= (const float*)d_in[26];
    float* out = (float*)d_out;

    const int attn_smem = 39432 * 4;
    const int edge_smem = (TM*SA + 128*SB) * 4;   // 210,944 B
    const int node_smem = 50944 * 4;
    cudaFuncSetAttribute(attn_kernel, cudaFuncAttributeMaxDynamicSharedMemorySize, attn_smem);
    cudaFuncSetAttribute(edge_kernel, cudaFuncAttributeMaxDynamicSharedMemorySize, edge_smem);
    cudaFuncSetAttribute(node_kernel, cudaFuncAttributeMaxDynamicSharedMemorySize, node_smem);

    prep_kernel<<<BB*TT + BB, 128>>>(cond, wk, bk, wv, bv, lat);
    zero_kernel<<<(NN*DD + 255) / 256, 256>>>();
    attn_kernel<<<152, 512, attn_smem>>>(node_features, frac, n2g,
                                         wq, bq, wo, bo, sw1, sb1, sw2, sb2);
    edge_kernel<<<EE / TM, 256, edge_smem>>>(frac, edges, e2g, ew1, eb1, ew2, eb2);
    node_kernel<<<152, 512, node_smem>>>(node_features, nw1, nb1, nw2, nb2, out);
}

// round 3
// speedup vs baseline: 2.9432x; 2.0508x over previous
#include <cuda_runtime.h>
#include <math.h>
#include <stdint.h>

#define NN 50000
#define EE 800000
#define BB 256
#define DD 128
#define TT 8
#define KV_OFF (BB*TT*DD)

// ---------------- scratch (no allocations allowed) ----------------
__device__ float g_h[(size_t)NN*DD];        // post-attention node states
__device__ float g_KV[2*BB*TT*DD];          // Kc then Vc
__device__ float g_lip[BB*9];               // lattice inner products
__device__ float g_agg[(size_t)NN*DD];      // scatter sums
__device__ int   g_cnt[NN];                 // scatter counts

__device__ __forceinline__ float silu_f(float x) {
    return __fdividef(x, 1.f + __expf(-x));
}

__device__ __forceinline__ void mma_tf32(float* c, const uint32_t* a, const uint32_t* b) {
    asm volatile(
        "mma.sync.aligned.m16n8k8.row.col.f32.tf32.tf32.f32 "
        "{%0,%1,%2,%3}, {%4,%5,%6,%7}, {%8,%9}, {%0,%1,%2,%3};\n"
        : "+f"(c[0]), "+f"(c[1]), "+f"(c[2]), "+f"(c[3])
        : "r"(a[0]), "r"(a[1]), "r"(a[2]), "r"(a[3]), "r"(b[0]), "r"(b[1]));
}

__device__ __forceinline__ void cpa16(float* dst, const float* src) {
    uint32_t d = (uint32_t)__cvta_generic_to_shared(dst);
    asm volatile("cp.async.cg.shared.global [%0], [%1], 16;" :: "r"(d), "l"(src));
}
#define CP_COMMIT asm volatile("cp.async.commit_group;" ::: "memory")
#define CP_WAIT0  asm volatile("cp.async.wait_group 0;" ::: "memory")

// ---------------- kernel 1: K/V projection + lattice gram ----------------
__global__ void prep_kernel(const float* __restrict__ cond,
                            const float* __restrict__ wk, const float* __restrict__ bk,
                            const float* __restrict__ wv, const float* __restrict__ bv,
                            const float* __restrict__ lat)
{
    int b = blockIdx.x;
    if (b < BB*TT) {
        __shared__ float s_c[DD];
        int d = threadIdx.x;
        s_c[d] = cond[b*DD + d];
        __syncthreads();
        float ka = bk[d], va = bv[d];
        #pragma unroll 8
        for (int k = 0; k < DD; k++) {
            float c = s_c[k];
            ka = fmaf(c, wk[k*DD + d], ka);
            va = fmaf(c, wv[k*DD + d], va);
        }
        g_KV[b*DD + d] = ka;
        g_KV[KV_OFF + b*DD + d] = va;
    } else {
        int bb = b - BB*TT;
        int t = threadIdx.x;
        if (t < 9) {
            int i = t / 3, k2 = t % 3;
            const float* L = lat + bb*9;
            g_lip[bb*9 + t] = L[i*3+0]*L[k2*3+0] + L[i*3+1]*L[k2*3+1] + L[i*3+2]*L[k2*3+2];
        }
    }
}

// ---------------- kernel 2: zero scatter buffers ----------------
__global__ void zero_kernel()
{
    int idx = blockIdx.x * blockDim.x + threadIdx.x;
    if (idx < NN*DD) g_agg[idx] = 0.f;
    if (idx < NN)    g_cnt[idx] = 0;
}

// ---------------- kernel 3: cross-attention with spatial bias ----------------
__global__ __launch_bounds__(512, 1)
void attn_kernel(const float* __restrict__ nfeat, const float* __restrict__ frac,
                 const int* __restrict__ n2g,
                 const float* __restrict__ wq, const float* __restrict__ bq,
                 const float* __restrict__ wo, const float* __restrict__ bo,
                 const float* __restrict__ sw1, const float* __restrict__ sb1,
                 const float* __restrict__ sw2, const float* __restrict__ sb2)
{
    extern __shared__ float sm[];
    float* s_wq  = sm;                 // 16384
    float* s_wo  = s_wq + 16384;       // 16384
    float* s_sw1 = s_wo + 16384;       // 3072
    float* s_sw2 = s_sw1 + 3072;       // 1024
    float* s_bq  = s_sw2 + 1024;       // 128
    float* s_bo  = s_bq + 128;         // 128
    float* s_sb1 = s_bo + 128;         // 128
    float* s_sb2 = s_sb1 + 128;        // 8
    float* s_h   = s_sb2 + 8;          // 512
    float* s_q   = s_h + 512;          // 512
    float* s_hid = s_q + 512;          // 512
    float* s_ca  = s_hid + 512;        // 512
    float* s_enc = s_ca + 512;         // 96
    float* s_att = s_enc + 96;         // 32

    int tid = threadIdx.x;
    for (int i = tid; i < 16384; i += 512) { s_wq[i] = wq[i]; s_wo[i] = wo[i]; }
    for (int i = tid; i < 3072; i += 512) s_sw1[i] = sw1[i];
    for (int i = tid; i < 1024; i += 512) s_sw2[i] = sw2[i];
    if (tid < 128) { s_bq[tid] = bq[tid]; s_bo[tid] = bo[tid]; s_sb1[tid] = sb1[tid]; }
    if (tid < 8) s_sb2[tid] = sb2[tid];
    __syncthreads();

    int sub = tid >> 7, d = tid & 127;
    int ngroups = (NN + 3) >> 2;
    for (int grp = blockIdx.x; grp < ngroups; grp += gridDim.x) {
        int n = grp*4 + sub;
        bool act = n < NN;
        int g = act ? n2g[n] : 0;
        float hv = act ? nfeat[(size_t)n*DD + d] : 0.f;
        s_h[sub*DD + d] = hv;
        if (d < 24 && act) {
            int ii = d % 12, c = ii >> 2, j = ii & 3;
            float ph = frac[n*3 + c] * ((float)(1 << j) * 3.14159265358979323846f);
            s_enc[sub*24 + d] = (d < 12) ? sinf(ph) : cosf(ph);
        }
        __syncthreads();

        {
            float acc = s_bq[d];
            const float* hh = s_h + sub*DD;
            #pragma unroll 8
            for (int k = 0; k < DD; k++) acc = fmaf(hh[k], s_wq[k*DD + d], acc);
            s_q[sub*DD + d] = acc;
            float ha = s_sb1[d];
            const float* ee = s_enc + sub*24;
            #pragma unroll
            for (int k = 0; k < 24; k++) ha = fmaf(ee[k], s_sw1[k*DD + d], ha);
            s_hid[sub*DD + d] = silu_f(ha);
        }
        __syncthreads();

        {
            int t = d >> 4, lane = d & 15;
            float sc = 0.f, bi = 0.f;
            const float* Kr = g_KV + ((size_t)(g*TT + t))*DD;
            const float* qq = s_q + sub*DD;
            const float* hh2 = s_hid + sub*DD;
            #pragma unroll
            for (int k = lane; k < DD; k += 16) {
                sc = fmaf(qq[k], Kr[k], sc);
                bi = fmaf(hh2[k], s_sw2[k*8 + t], bi);
            }
            #pragma unroll
            for (int o = 8; o > 0; o >>= 1) {
                sc += __shfl_down_sync(0xffffffffu, sc, o, 16);
                bi += __shfl_down_sync(0xffffffffu, bi, o, 16);
            }
            if (lane == 0)
                s_att[sub*8 + t] = sc * 0.08838834764831845f + bi + s_sb2[t];
        }
        __syncthreads();
        if (d == 0) {
            float* a = s_att + sub*8;
            float m = a[0];
            #pragma unroll
            for (int u = 1; u < 8; u++) m = fmaxf(m, a[u]);
            float s = 0.f, ex[8];
            #pragma unroll
            for (int u = 0; u < 8; u++) { ex[u] = __expf(a[u] - m); s += ex[u]; }
            float inv = __fdividef(1.f, s);
            #pragma unroll
            for (int u = 0; u < 8; u++) a[u] = ex[u] * inv;
        }
        __syncthreads();
        {
            const float* Vr = g_KV + KV_OFF + ((size_t)(g*TT))*DD;
            float ca = 0.f;
            #pragma unroll
            for (int u = 0; u < 8; u++) ca = fmaf(s_att[sub*8 + u], Vr[u*DD + d], ca);
            s_ca[sub*DD + d] = ca;
        }
        __syncthreads();
        {
            float out = hv + s_bo[d];
            const float* cc = s_ca + sub*DD;
            #pragma unroll 8
            for (int k = 0; k < DD; k++) out = fmaf(cc[k], s_wo[k*DD + d], out);
            if (act) g_h[(size_t)n*DD + d] = out;
        }
        __syncthreads();
    }
}

// ---------------- kernel 4: edge MLP, 16 warps, cp.async pipelined ----------------
// Block tile: 128 edges x 128 outs. 16 warps 4x4, warp tile 32x32 (2 mfrag x 4 nfrag).
#define TM 128
#define SA 276     // A row stride; 276%32=20 -> conflict-free frags
#define SB 136     // B row stride; 136%32=8  -> conflict-free frags
#define BBF (16*SB)

__global__ __launch_bounds__(512, 1)
void edge_kernel(const float* __restrict__ frac,
                 const int* __restrict__ edges, const int* __restrict__ e2g,
                 const float* __restrict__ ew1, const float* __restrict__ eb1,
                 const float* __restrict__ ew2, const float* __restrict__ eb2)
{
    extern __shared__ float sm[];
    float* s_a  = sm;             // TM*SA
    float* s_bb = sm + TM*SA;     // 2*BBF double buffer
    __shared__ int s_i[TM], s_j[TM];

    int tid  = threadIdx.x;
    int lane = tid & 31;
    int wid  = tid >> 5;
    int wm = wid >> 2;            // 0..3
    int wn = wid & 3;             // 0..3
    int e0 = blockIdx.x * TM;
    int brow = tid >> 5, bc4 = (tid & 31) * 4;   // B chunk coop-load coords

    if (tid < TM) {
        s_i[tid] = edges[e0 + tid];
        s_j[tid] = edges[EE + e0 + tid];
    }
    __syncthreads();

    // async gather A (raw fp32; HMMA truncates to tf32)
    #pragma unroll
    for (int it = 0; it < 16; it++) {
        int idx = tid + it*512;
        int r = idx >> 5, c4 = (idx & 31) * 4;
        int e = r >> 1, p = r & 1;
        int node = p ? s_j[e] : s_i[e];
        cpa16(s_a + e*SA + p*DD + c4, g_h + (size_t)node*DD + c4);
    }
    // ew1 chunk 0 -> buf0
    cpa16(s_bb + brow*SB + bc4, ew1 + (size_t)brow*DD + bc4);
    CP_COMMIT;

    // scalar tail columns + counts (overlap with cp.async flight)
    if (tid < TM) {
        int e = tid;
        const float* lp = g_lip + e2g[e0 + e]*9;
        #pragma unroll
        for (int u = 0; u < 9; u++) s_a[e*SA + 256 + u] = lp[u];
        int ii = s_i[e], jj = s_j[e];
        #pragma unroll
        for (int c = 0; c < 3; c++) {
            float dd = frac[jj*3 + c] - frac[ii*3 + c];
            dd -= floorf(dd);
            s_a[e*SA + 265 + c] = dd;
        }
        #pragma unroll
        for (int u = 268; u < 276; u++) s_a[e*SA + u] = 0.f;
        atomicAdd(&g_cnt[ii], 1);
    }

    float acc[2][4][4];
    #pragma unroll
    for (int mf = 0; mf < 2; mf++)
        #pragma unroll
        for (int nf = 0; nf < 4; nf++)
            #pragma unroll
            for (int u = 0; u < 4; u++) acc[mf][nf][u] = 0.f;

    CP_WAIT0;
    __syncthreads();

    // ---- GEMM1: 17 chunks of 16 k-rows (k=272; invalid rows clamp to 267, A cols zero) ----
    for (int ct = 0; ct < 17; ct++) {
        if (ct < 16) {
            int kr = min(ct*16 + 16 + brow, 267);
            cpa16(s_bb + ((ct+1)&1)*BBF + brow*SB + bc4, ew1 + (size_t)kr*DD + bc4);
        } else {
            // prefetch ew2 chunk 0 -> buf1 ((17)&1 == 1)
            cpa16(s_bb + BBF + brow*SB + bc4, ew2 + (size_t)brow*DD + bc4);
        }
        CP_COMMIT;

        const float* bB = s_bb + (ct & 1)*BBF;
        #pragma unroll
        for (int kk = 0; kk < 16; kk += 8) {
            int kg = ct*16 + kk;
            uint32_t afr[2][4];
            #pragma unroll
            for (int mf = 0; mf < 2; mf++) {
                const float* ap = s_a + (wm*32 + mf*16 + (lane >> 2))*SA + kg + (lane & 3);
                afr[mf][0] = __float_as_uint(ap[0]);
                afr[mf][1] = __float_as_uint(ap[8*SA]);
                afr[mf][2] = __float_as_uint(ap[4]);
                afr[mf][3] = __float_as_uint(ap[8*SA + 4]);
            }
            uint32_t bfr[4][2];
            #pragma unroll
            for (int nf = 0; nf < 4; nf++) {
                const float* bp = bB + (kk + (lane & 3))*SB + wn*32 + nf*8 + (lane >> 2);
                bfr[nf][0] = __float_as_uint(bp[0]);
                bfr[nf][1] = __float_as_uint(bp[4*SB]);
            }
            #pragma unroll
            for (int mf = 0; mf < 2; mf++)
                #pragma unroll
                for (int nf = 0; nf < 4; nf++)
                    mma_tf32(acc[mf][nf], afr[mf], bfr[nf]);
        }
        CP_WAIT0;
        __syncthreads();
    }

    // ---- hidden = silu(acc + eb1) -> s_a cols 0..127 ----
    #pragma unroll
    for (int mf = 0; mf < 2; mf++) {
        int r0 = wm*32 + mf*16 + (lane >> 2);
        #pragma unroll
        for (int nf = 0; nf < 4; nf++) {
            int n = wn*32 + nf*8 + (lane & 3)*2;
            float b0 = eb1[n], b1 = eb1[n + 1];
            s_a[r0*SA + n]           = silu_f(acc[mf][nf][0] + b0);
            s_a[r0*SA + n + 1]       = silu_f(acc[mf][nf][1] + b1);
            s_a[(r0 + 8)*SA + n]     = silu_f(acc[mf][nf][2] + b0);
            s_a[(r0 + 8)*SA + n + 1] = silu_f(acc[mf][nf][3] + b1);
            #pragma unroll
            for (int u = 0; u < 4; u++) acc[mf][nf][u] = 0.f;
        }
    }
    __syncthreads();

    // ---- GEMM2: 8 chunks of ew2; chunk c lives in buf[(1+c)&1] ----
    for (int c = 0; c < 8; c++) {
        if (c < 7) {
            cpa16(s_bb + (c & 1)*BBF + brow*SB + bc4,
                  ew2 + (size_t)(c*16 + 16 + brow)*DD + bc4);
            CP_COMMIT;
        }
        const float* bB = s_bb + ((1 + c) & 1)*BBF;
        #pragma unroll
        for (int kk = 0; kk < 16; kk += 8) {
            int kg = c*16 + kk;
            uint32_t afr[2][4];
            #pragma unroll
            for (int mf = 0; mf < 2; mf++) {
                const float* ap = s_a + (wm*32 + mf*16 + (lane >> 2))*SA + kg + (lane & 3);
                afr[mf][0] = __float_as_uint(ap[0]);
                afr[mf][1] = __float_as_uint(ap[8*SA]);
                afr[mf][2] = __float_as_uint(ap[4]);
                afr[mf][3] = __float_as_uint(ap[8*SA + 4]);
            }
            uint32_t bfr[4][2];
            #pragma unroll
            for (int nf = 0; nf < 4; nf++) {
                const float* bp = bB + (kk + (lane & 3))*SB + wn*32 + nf*8 + (lane >> 2);
                bfr[nf][0] = __float_as_uint(bp[0]);
                bfr[nf][1] = __float_as_uint(bp[4*SB]);
            }
            #pragma unroll
            for (int mf = 0; mf < 2; mf++)
                #pragma unroll
                for (int nf = 0; nf < 4; nf++)
                    mma_tf32(acc[mf][nf], afr[mf], bfr[nf]);
        }
        if (c < 7) { CP_WAIT0; }
        __syncthreads();
    }

    // ---- epilogue: silu + bias, vector red scatter into g_agg ----
    #pragma unroll
    for (int mf = 0; mf < 2; mf++) {
        #pragma unroll
        for (int rr = 0; rr < 2; rr++) {
            int m = wm*32 + mf*16 + (lane >> 2) + rr*8;
            float* ap = g_agg + (size_t)s_i[m]*DD;
            #pragma unroll
            for (int nf = 0; nf < 4; nf++) {
                int n = wn*32 + nf*8 + (lane & 3)*2;
                float v0 = silu_f(acc[mf][nf][rr*2 + 0] + eb2[n]);
                float v1 = silu_f(acc[mf][nf][rr*2 + 1] + eb2[n + 1]);
                asm volatile("red.global.add.v2.f32 [%0], {%1, %2};"
                             :: "l"(ap + n), "f"(v0), "f"(v1) : "memory");
            }
        }
    }
}

// ---------------- kernel 5: node MLP via tf32 mma, cp.async pipelined ----------------
#define TN 128
#define SA2 260    // 260%32=4 -> conflict-free frags

__global__ __launch_bounds__(512, 1)
void node_kernel(const float* __restrict__ nfeat,
                 const float* __restrict__ nw1, const float* __restrict__ nb1,
                 const float* __restrict__ nw2, const float* __restrict__ nb2,
                 float* __restrict__ out)
{
    extern __shared__ float sm[];
    float* s_a  = sm;              // TN*SA2
    float* s_bb = sm + TN*SA2;     // 2*BBF
    __shared__ float s_cnt[TN];

    int tid  = threadIdx.x;
    int lane = tid & 31;
    int wid  = tid >> 5;
    int wm = wid >> 2, wn = wid & 3;
    int n0 = blockIdx.x * TN;
    int brow = tid >> 5, bc4 = (tid & 31) * 4;

    if (tid < TN) {
        int n = min(n0 + tid, NN - 1);
        s_cnt[tid] = fmaxf((float)g_cnt[n], 1.f);
    }
    // async load h rows (cols 0..127)
    #pragma unroll
    for (int it = 0; it < 8; it++) {
        int idx = tid + it*512;
        int r = idx >> 5, c4 = (idx & 31) * 4;
        int n = min(n0 + r, NN - 1);
        cpa16(s_a + r*SA2 + c4, g_h + (size_t)n*DD + c4);
    }
    // nw1 chunk 0 -> buf0
    cpa16(s_bb + brow*SB + bc4, nw1 + (size_t)brow*DD + bc4);
    CP_COMMIT;
    __syncthreads();   // s_cnt visible

    // agg/cnt -> cols 128..255 (scalar path, divides)
    for (int it = 0; it < 8; it++) {
        int idx = tid + it*512;
        int r = idx >> 5, c4 = (idx & 31) * 4;
        int n = min(n0 + r, NN - 1);
        float inv = __fdividef(1.f, s_cnt[r]);
        float4 v = *(const float4*)(g_agg + (size_t)n*DD + c4);
        float* dst = s_a + r*SA2 + DD + c4;
        dst[0] = v.x * inv; dst[1] = v.y * inv; dst[2] = v.z * inv; dst[3] = v.w * inv;
    }

    float acc[2][4][4];
    #pragma unroll
    for (int mf = 0; mf < 2; mf++)
        #pragma unroll
        for (int nf = 0; nf < 4; nf++)
            #pragma unroll
            for (int u = 0; u < 4; u++) acc[mf][nf][u] = 0.f;

    CP_WAIT0;
    __syncthreads();

    // ---- GEMM1: [128,256] x nw1[256,128], 16 chunks ----
    for (int ct = 0; ct < 16; ct++) {
        if (ct < 15) {
            cpa16(s_bb + ((ct+1)&1)*BBF + brow*SB + bc4,
                  nw1 + (size_t)(ct*16 + 16 + brow)*DD + bc4);
        } else {
            cpa16(s_bb + ((ct+1)&1)*BBF + brow*SB + bc4,   // nw2 chunk0 -> buf0
                  nw2 + (size_t)brow*DD + bc4);
        }
        CP_COMMIT;
        const float* bB = s_bb + (ct & 1)*BBF;
        #pragma unroll
        for (int kk = 0; kk < 16; kk += 8) {
            int kg = ct*16 + kk;
            uint32_t afr[2][4];
            #pragma unroll
            for (int mf = 0; mf < 2; mf++) {
                const float* ap = s_a + (wm*32 + mf*16 + (lane >> 2))*SA2 + kg + (lane & 3);
                afr[mf][0] = __float_as_uint(ap[0]);
                afr[mf][1] = __float_as_uint(ap[8*SA2]);
                afr[mf][2] = __float_as_uint(ap[4]);
                afr[mf][3] = __float_as_uint(ap[8*SA2 + 4]);
            }
            uint32_t bfr[4][2];
            #pragma unroll
            for (int nf = 0; nf < 4; nf++) {
                const float* bp = bB + (kk + (lane & 3))*SB + wn*32 + nf*8 + (lane >> 2);
                bfr[nf][0] = __float_as_uint(bp[0]);
                bfr[nf][1] = __float_as_uint(bp[4*SB]);
            }
            #pragma unroll
            for (int mf = 0; mf < 2; mf++)
                #pragma unroll
                for (int nf = 0; nf < 4; nf++)
                    mma_tf32(acc[mf][nf], afr[mf], bfr[nf]);
        }
        CP_WAIT0;
        __syncthreads();
    }

    // hidden -> s_a cols 0..127
    #pragma unroll
    for (int mf = 0; mf < 2; mf++) {
        int r0 = wm*32 + mf*16 + (lane >> 2);
        #pragma unroll
        for (int nf = 0; nf < 4; nf++) {
            int n = wn*32 + nf*8 + (lane & 3)*2;
            float b0 = nb1[n], b1 = nb1[n + 1];
            s_a[r0*SA2 + n]           = silu_f(acc[mf][nf][0] + b0);
            s_a[r0*SA2 + n + 1]       = silu_f(acc[mf][nf][1] + b1);
            s_a[(r0 + 8)*SA2 + n]     = silu_f(acc[mf][nf][2] + b0);
            s_a[(r0 + 8)*SA2 + n + 1] = silu_f(acc[mf][nf][3] + b1);
            #pragma unroll
            for (int u = 0; u < 4; u++) acc[mf][nf][u] = 0.f;
        }
    }
    __syncthreads();

    // ---- GEMM2: [128,128] x nw2[128,128], 8 chunks; chunk c in buf[c&1] ----
    for (int c = 0; c < 8; c++) {
        if (c < 7) {
            cpa16(s_bb + ((c+1)&1)*BBF + brow*SB + bc4,
                  nw2 + (size_t)(c*16 + 16 + brow)*DD + bc4);
            CP_COMMIT;
        }
        const float* bB = s_bb + (c & 1)*BBF;
        #pragma unroll
        for (int kk = 0; kk < 16; kk += 8) {
            int kg = c*16 + kk;
            uint32_t afr[2][4];
            #pragma unroll
            for (int mf = 0; mf < 2; mf++) {
                const float* ap = s_a + (wm*32 + mf*16 + (lane >> 2))*SA2 + kg + (lane & 3);
                afr[mf][0] = __float_as_uint(ap[0]);
                afr[mf][1] = __float_as_uint(ap[8*SA2]);
                afr[mf][2] = __float_as_uint(ap[4]);
                afr[mf][3] = __float_as_uint(ap[8*SA2 + 4]);
            }
            uint32_t bfr[4][2];
            #pragma unroll
            for (int nf = 0; nf < 4; nf++) {
                const float* bp = bB + (kk + (lane & 3))*SB + wn*32 + nf*8 + (lane >> 2);
                bfr[nf][0] = __float_as_uint(bp[0]);
                bfr[nf][1] = __float_as_uint(bp[4*SB]);
            }
            #pragma unroll
            for (int mf = 0; mf < 2; mf++)
                #pragma unroll
                for (int nf = 0; nf < 4; nf++)
                    mma_tf32(acc[mf][nf], afr[mf], bfr[nf]);
        }
        if (c < 7) { CP_WAIT0; }
        __syncthreads();
    }

    // epilogue: out = nfeat + silu(acc + nb2)
    #pragma unroll
    for (int mf = 0; mf < 2; mf++) {
        #pragma unroll
        for (int rr = 0; rr < 2; rr++) {
            int m = wm*32 + mf*16 + (lane >> 2) + rr*8;
            int n = n0 + m;
            if (n < NN) {
                const float* nfr = nfeat + (size_t)n*DD;
                float* orow = out + (size_t)n*DD;
                #pragma unroll
                for (int nf = 0; nf < 4; nf++) {
                    int col = wn*32 + nf*8 + (lane & 3)*2;
                    orow[col]     = nfr[col]     + silu_f(acc[mf][nf][rr*2 + 0] + nb2[col]);
                    orow[col + 1] = nfr[col + 1] + silu_f(acc[mf][nf][rr*2 + 1] + nb2[col + 1]);
                }
            }
        }
    }
}

// ---------------- launch ----------------
extern "C" void kernel_launch(void* const* d_in, const int* in_sizes, int n_in,
                              void* d_out, int out_size)
{
    const float* node_features = (const float*)d_in[0];
    const float* cond = (const float*)d_in[1];
    const int*   n2g  = (const int*)d_in[2];
    const float* frac = (const float*)d_in[3];
    const float* lat  = (const float*)d_in[4];
    const int*   edges= (const int*)d_in[5];
    const int*   e2g  = (const int*)d_in[6];
    const float* wq = (const float*)d_in[7];
    const float* bq = (const float*)d_in[8];
    const float* wk = (const float*)d_in[9];
    const float* bk = (const float*)d_in[10];
    const float* wv = (const float*)d_in[11];
    const float* bv = (const float*)d_in[12];
    const float* wo = (const float*)d_in[13];
    const float* bo = (const float*)d_in[14];
    const float* sw1= (const float*)d_in[15];
    const float* sb1= (const float*)d_in[16];
    const float* sw2= (const float*)d_in[17];
    const float* sb2= (const float*)d_in[18];
    const float* ew1= (const float*)d_in[19];
    const float* eb1= (const float*)d_in[20];
    const float* ew2= (const float*)d_in[21];
    const float* eb2= (const float*)d_in[22];
    const float* nw1= (const float*)d_in[23];
    const float* nb1= (const float*)d_in[24];
    const float* nw2= (const float*)d_in[25];
    const float* nb2= (const float*)d_in[26];
    float* out = (float*)d_out;

    const int attn_smem = 39432 * 4;
    const int edge_smem = (TM*SA + 2*BBF) * 4;    // 158,720 B
    const int node_smem = (TN*SA2 + 2*BBF) * 4;   // 150,528 B
    cudaFuncSetAttribute(attn_kernel, cudaFuncAttributeMaxDynamicSharedMemorySize, attn_smem);
    cudaFuncSetAttribute(edge_kernel, cudaFuncAttributeMaxDynamicSharedMemorySize, edge_smem);
    cudaFuncSetAttribute(node_kernel, cudaFuncAttributeMaxDynamicSharedMemorySize, node_smem);

    prep_kernel<<<BB*TT + BB, 128>>>(cond, wk, bk, wv, bv, lat);
    zero_kernel<<<(NN*DD + 255) / 256, 256>>>();
    attn_kernel<<<152, 512, attn_smem>>>(node_features, frac, n2g,
                                         wq, bq, wo, bo, sw1, sb1, sw2, sb2);
    edge_kernel<<<EE / TM, 512, edge_smem>>>(frac, edges, e2g, ew1, eb1, ew2, eb2);
    node_kernel<<<(NN + TN - 1) / TN, 512, node_smem>>>(node_features, nw1, nb1, nw2, nb2, out);
}